// round 4
// baseline (speedup 1.0000x reference)
#include <cuda_runtime.h>

// PatchChamferDistance: B=32, G=64, P=256, D=3 (fp32)
// d2[i][j] = max(|p_i|^2 + |q_j|^2 - 2 p_i.q_j, 0)
// out = mean_patch( mean_i min_j d2 + mean_j min_i d2 )
//
// R4: 128 thr/CTA, 2 pred + 2 tgt rows per thread, rows packed as f32x2.
// Scan operand duplicated+prescaled in smem:
//   A[j] = {-2x,-2x,-2y,-2y}   B[j] = {-2z,-2z, w, w}
// Fold: d = pw + (qw - 2 dot); pw const over scan -> add once after loop.
// Inner loop per j per direction: 2 LDS.128 + 3 fma.f32x2 + 2 FMNMX.

#define BGQ  2048
#define NP   256
#define T    128
#define INF  3.402823e38f

typedef unsigned long long u64;

__device__ __forceinline__ u64 pk2(float a, float b) {
    u64 r;
    asm("mov.b64 %0, {%1, %2};" : "=l"(r) : "f"(a), "f"(b));
    return r;
}
__device__ __forceinline__ u64 fma2(u64 a, u64 b, u64 c) {
    u64 d;
    asm("fma.rn.f32x2 %0, %1, %2, %3;" : "=l"(d) : "l"(a), "l"(b), "l"(c));
    return d;
}
__device__ __forceinline__ void upk2(u64 v, float& lo, float& hi) {
    asm("mov.b64 {%0, %1}, %2;" : "=f"(lo), "=f"(hi) : "l"(v));
}

__global__ void pcd_zero_kernel(float* out) { out[0] = 0.0f; }

__global__ __launch_bounds__(T)
void pcd_chamfer_kernel(const float* __restrict__ pred,
                        const float* __restrict__ tgt,
                        float* __restrict__ out)
{
    __shared__ ulonglong2 sqA[NP], sqB[NP];   // targets (duplicated, prescaled)
    __shared__ ulonglong2 spA[NP], spB[NP];   // preds
    __shared__ float wsum[T / 32];

    const int patch = blockIdx.x;
    const int t     = threadIdx.x;

    const float* pb = pred + (size_t)patch * NP * 3;
    const float* qb = tgt  + (size_t)patch * NP * 3;

    // owned rows: j = t (lo half) and j = t+128 (hi half)
    float prw[2], trw[2];          // norms of owned rows (added after loop)
    float prx[2], pry[2], prz[2];
    float trx[2], tryy[2], trz[2];

#pragma unroll
    for (int r = 0; r < 2; r++) {
        int j = t + T * r;
        float x = pb[j * 3 + 0], y = pb[j * 3 + 1], z = pb[j * 3 + 2];
        float w = x * x + y * y + z * z;
        prx[r] = x; pry[r] = y; prz[r] = z; prw[r] = w;
        spA[j] = make_ulonglong2(pk2(-2.f * x, -2.f * x), pk2(-2.f * y, -2.f * y));
        spB[j] = make_ulonglong2(pk2(-2.f * z, -2.f * z), pk2(w, w));

        x = qb[j * 3 + 0]; y = qb[j * 3 + 1]; z = qb[j * 3 + 2];
        w = x * x + y * y + z * z;
        trx[r] = x; tryy[r] = y; trz[r] = z; trw[r] = w;
        sqA[j] = make_ulonglong2(pk2(-2.f * x, -2.f * x), pk2(-2.f * y, -2.f * y));
        sqB[j] = make_ulonglong2(pk2(-2.f * z, -2.f * z), pk2(w, w));
    }
    __syncthreads();

    // pack owned coords (both rows) into f32x2 pairs
    u64 px = pk2(prx[0], prx[1]), py = pk2(pry[0], pry[1]), pz = pk2(prz[0], prz[1]);
    u64 qx = pk2(trx[0], trx[1]), qy = pk2(tryy[0], tryy[1]), qz = pk2(trz[0], trz[1]);

    // accumulate min over j of (scan_w - 2*dot); own-row norm added after loop
    float fmn0 = INF, fmn1 = INF;   // forward (pred rows)
    float bmn0 = INF, bmn1 = INF;   // backward (tgt rows)

#pragma unroll 8
    for (int j = 0; j < NP; j++) {
        {   // forward: owned pred rows vs target j
            ulonglong2 a = sqA[j];           // {-2qx,-2qx},{-2qy,-2qy}
            ulonglong2 b = sqB[j];           // {-2qz,-2qz},{ qw,  qw }
            u64 acc = fma2(px, a.x, b.y);
            acc = fma2(py, a.y, acc);
            acc = fma2(pz, b.x, acc);
            float d0, d1; upk2(acc, d0, d1); // reg-pair halves: free
            fmn0 = fminf(fmn0, d0);
            fmn1 = fminf(fmn1, d1);
        }
        {   // backward: owned tgt rows vs pred j
            ulonglong2 a = spA[j];
            ulonglong2 b = spB[j];
            u64 acc = fma2(qx, a.x, b.y);
            acc = fma2(qy, a.y, acc);
            acc = fma2(qz, b.x, acc);
            float d0, d1; upk2(acc, d0, d1);
            bmn0 = fminf(bmn0, d0);
            bmn1 = fminf(bmn1, d1);
        }
    }

    // add own-row norm, clamp (commutes with min), sum 4 row contributions
    float v = fmaxf(prw[0] + fmn0, 0.f) + fmaxf(prw[1] + fmn1, 0.f)
            + fmaxf(trw[0] + bmn0, 0.f) + fmaxf(trw[1] + bmn1, 0.f);

    // block reduction: 4 warps
#pragma unroll
    for (int o = 16; o > 0; o >>= 1)
        v += __shfl_down_sync(0xffffffffu, v, o);
    if ((t & 31) == 0) wsum[t >> 5] = v;
    __syncthreads();
    if (t == 0) {
        float s = wsum[0] + wsum[1] + wsum[2] + wsum[3];
        atomicAdd(out, s * (1.0f / ((float)NP * (float)BGQ)));
    }
}

extern "C" void kernel_launch(void* const* d_in, const int* in_sizes, int n_in,
                              void* d_out, int out_size)
{
    const float* pred = (const float*)d_in[0];
    const float* tgt  = (const float*)d_in[1];
    float* out = (float*)d_out;

    pcd_zero_kernel<<<1, 1>>>(out);
    pcd_chamfer_kernel<<<BGQ, T>>>(pred, tgt, out);
}

// round 5
// speedup vs baseline: 1.6818x; 1.6818x over previous
#include <cuda_runtime.h>

// PatchChamferDistance: B=32, G=64, P=256, D=3 (fp32)
// d2[i][j] = max(|p_i|^2 + |q_j|^2 - 2 p_i.q_j, 0)
// out = mean_patch( mean_i min_j d2 + mean_j min_i d2 )
//
// R5: pair-packed scan + 4 rows/thread.
//  smem per cloud: A2[jj] = {-2x_j0,-2x_j1, -2y_j0,-2y_j1}
//                  B2[jj] = {-2z_j0,-2z_j1,  w_j0,  w_j1 }   (16B/point)
//  Own row packed once as {p,p}; each fma2 chain = 1 row vs 2 scan points:
//     acc = fma2(pz2, B.x, fma2(py2, A.y, fma2(px2, A.x, B.y)))
//     halves = {qw - 2 p.q}(j0), (j1); own norm added after the loop.
//  64 threads per patch, 2 patches per 128-thread CTA.

#define BGQ   2048
#define NP    256
#define NPAIR 128
#define T     128
#define INF   3.402823e38f

typedef unsigned long long u64;

__device__ __forceinline__ u64 pk2(float a, float b) {
    u64 r;
    asm("mov.b64 %0, {%1, %2};" : "=l"(r) : "f"(a), "f"(b));
    return r;
}
__device__ __forceinline__ u64 fma2(u64 a, u64 b, u64 c) {
    u64 d;
    asm("fma.rn.f32x2 %0, %1, %2, %3;" : "=l"(d) : "l"(a), "l"(b), "l"(c));
    return d;
}
__device__ __forceinline__ void upk2(u64 v, float& lo, float& hi) {
    asm("mov.b64 {%0, %1}, %2;" : "=f"(lo), "=f"(hi) : "l"(v));
}

__global__ void pcd_zero_kernel(float* out) { out[0] = 0.0f; }

__global__ __launch_bounds__(T)
void pcd_chamfer_kernel(const float* __restrict__ pred,
                        const float* __restrict__ tgt,
                        float* __restrict__ out)
{
    __shared__ ulonglong2 sqA[2][NPAIR], sqB[2][NPAIR];   // targets, per patch
    __shared__ ulonglong2 spA[2][NPAIR], spB[2][NPAIR];   // preds
    __shared__ float wsum[4];

    const int t  = threadIdx.x;
    const int ps = t >> 6;          // patch slot in CTA (0/1)
    const int t2 = t & 63;          // lane within patch group
    const int patch = blockIdx.x * 2 + ps;

    const float* pb = pred + (size_t)patch * NP * 3;
    const float* qb = tgt  + (size_t)patch * NP * 3;

    // this thread owns points 2*t2, 2*t2+1, 2*t2+128, 2*t2+129 of each cloud
    float prx[4], pry[4], prz[4], prw[4];
    float trx[4], tryy[4], trz[4], trw[4];

#pragma unroll
    for (int h = 0; h < 2; h++) {
        int jj = t2 + 64 * h;
        int j0 = 2 * jj;

        float x0 = pb[j0 * 3 + 0], y0 = pb[j0 * 3 + 1], z0 = pb[j0 * 3 + 2];
        float x1 = pb[j0 * 3 + 3], y1 = pb[j0 * 3 + 4], z1 = pb[j0 * 3 + 5];
        float w0 = x0 * x0 + y0 * y0 + z0 * z0;
        float w1 = x1 * x1 + y1 * y1 + z1 * z1;
        spA[ps][jj] = make_ulonglong2(pk2(-2.f * x0, -2.f * x1), pk2(-2.f * y0, -2.f * y1));
        spB[ps][jj] = make_ulonglong2(pk2(-2.f * z0, -2.f * z1), pk2(w0, w1));
        prx[2*h] = x0; pry[2*h] = y0; prz[2*h] = z0; prw[2*h] = w0;
        prx[2*h+1] = x1; pry[2*h+1] = y1; prz[2*h+1] = z1; prw[2*h+1] = w1;

        x0 = qb[j0 * 3 + 0]; y0 = qb[j0 * 3 + 1]; z0 = qb[j0 * 3 + 2];
        x1 = qb[j0 * 3 + 3]; y1 = qb[j0 * 3 + 4]; z1 = qb[j0 * 3 + 5];
        w0 = x0 * x0 + y0 * y0 + z0 * z0;
        w1 = x1 * x1 + y1 * y1 + z1 * z1;
        sqA[ps][jj] = make_ulonglong2(pk2(-2.f * x0, -2.f * x1), pk2(-2.f * y0, -2.f * y1));
        sqB[ps][jj] = make_ulonglong2(pk2(-2.f * z0, -2.f * z1), pk2(w0, w1));
        trx[2*h] = x0; tryy[2*h] = y0; trz[2*h] = z0; trw[2*h] = w0;
        trx[2*h+1] = x1; tryy[2*h+1] = y1; trz[2*h+1] = z1; trw[2*h+1] = w1;
    }
    __syncthreads();

    // own rows packed {v,v} once (outside the loop)
    u64 px2[4], py2[4], pz2[4], qx2[4], qy2[4], qz2[4];
#pragma unroll
    for (int r = 0; r < 4; r++) {
        px2[r] = pk2(prx[r], prx[r]);
        py2[r] = pk2(pry[r], pry[r]);
        pz2[r] = pk2(prz[r], prz[r]);
        qx2[r] = pk2(trx[r], trx[r]);
        qy2[r] = pk2(tryy[r], tryy[r]);
        qz2[r] = pk2(trz[r], trz[r]);
    }

    float fmn[4] = {INF, INF, INF, INF};   // min_j (qw - 2 p.q) per owned pred row
    float bmn[4] = {INF, INF, INF, INF};   // min_i (pw - 2 q.p) per owned tgt row

#pragma unroll 4
    for (int jj = 0; jj < NPAIR; jj++) {
        {   // forward: 4 owned pred rows vs target pair jj
            ulonglong2 a = sqA[ps][jj];    // warp-uniform -> broadcast
            ulonglong2 b = sqB[ps][jj];
#pragma unroll
            for (int r = 0; r < 4; r++) {
                u64 acc = fma2(px2[r], a.x, b.y);
                acc = fma2(py2[r], a.y, acc);
                acc = fma2(pz2[r], b.x, acc);
                float d0, d1; upk2(acc, d0, d1);
                fmn[r] = fminf(fmn[r], fminf(d0, d1));
            }
        }
        {   // backward: 4 owned tgt rows vs pred pair jj
            ulonglong2 a = spA[ps][jj];
            ulonglong2 b = spB[ps][jj];
#pragma unroll
            for (int r = 0; r < 4; r++) {
                u64 acc = fma2(qx2[r], a.x, b.y);
                acc = fma2(qy2[r], a.y, acc);
                acc = fma2(qz2[r], b.x, acc);
                float d0, d1; upk2(acc, d0, d1);
                bmn[r] = fminf(bmn[r], fminf(d0, d1));
            }
        }
    }

    // add own norms, clamp (commutes with min), sum 8 row contributions
    float v = 0.f;
#pragma unroll
    for (int r = 0; r < 4; r++)
        v += fmaxf(prw[r] + fmn[r], 0.f) + fmaxf(trw[r] + bmn[r], 0.f);

    // warp reduce, then per-patch combine (warps 0,1 -> patch0; 2,3 -> patch1)
#pragma unroll
    for (int o = 16; o > 0; o >>= 1)
        v += __shfl_down_sync(0xffffffffu, v, o);
    if ((t & 31) == 0) wsum[t >> 5] = v;
    __syncthreads();
    if (t < 2) {
        float s = wsum[2 * t] + wsum[2 * t + 1];
        atomicAdd(out, s * (1.0f / ((float)NP * (float)BGQ)));
    }
}

extern "C" void kernel_launch(void* const* d_in, const int* in_sizes, int n_in,
                              void* d_out, int out_size)
{
    const float* pred = (const float*)d_in[0];
    const float* tgt  = (const float*)d_in[1];
    float* out = (float*)d_out;

    pcd_zero_kernel<<<1, 1>>>(out);
    pcd_chamfer_kernel<<<BGQ / 2, T>>>(pred, tgt, out);
}